// round 9
// baseline (speedup 1.0000x reference)
#include <cuda_runtime.h>
#include <cuda_fp16.h>
#include <cstdint>

// ---------------------------------------------------------------------------
// Problem constants
// ---------------------------------------------------------------------------
#define DIM    1024
#define FPN    512
#define NOUT   2048
#define MROWS  65536            // 16*4*32*32

// GEMM tiling: CTA 128x256, 8 warps of 64x64, BK=32, 4 stages
#define TM 128
#define TN 256
#define BK 32
#define NCHUNK (DIM / BK)       // 32
#define STAGES 4                // power of two -> & (STAGES-1) indexing

// SMEM: padded rows of 80B (32 fp16 = 64B data + 16B pad) -> conflict-free ldmatrix
#define ROWB 80
#define OFF_A 0
#define A_BYTES (128 * ROWB)            // 10240
#define OFF_B A_BYTES
#define B_BYTES (256 * ROWB)            // 20480
#define STAGE_BYTES (A_BYTES + B_BYTES) // 30720
#define SMEM_TOTAL (STAGES * STAGE_BYTES)  // 122880 -> 1 CTA/SM

// ---------------------------------------------------------------------------
// Device scratch (device globals; no dynamic allocation allowed)
// ---------------------------------------------------------------------------
__device__ float g_scale[MROWS];                 // rstd
__device__ float g_shift[MROWS];                 // rstd * mu
__device__ __half g_Ah[(size_t)MROWS * DIM];     // 128 MB
__device__ __half g_Bh[(size_t)NOUT * DIM];      // 4 MB
__device__ float g_s1[NOUT];
__device__ float g_s2[NOUT];

// ---------------------------------------------------------------------------
// PTX helpers (base PTX, family-generic sm_103 safe)
// ---------------------------------------------------------------------------
__device__ __forceinline__ uint32_t smem_u32(const void* p) {
    uint32_t a;
    asm("{ .reg .u64 t; cvta.to.shared.u64 t, %1; cvt.u32.u64 %0, t; }"
        : "=r"(a) : "l"(p));
    return a;
}
__device__ __forceinline__ void cpasync16(uint32_t dst, const void* src) {
    asm volatile("cp.async.cg.shared.global [%0], [%1], 16;"
                 :: "r"(dst), "l"(src));
}
__device__ __forceinline__ void cp_commit() {
    asm volatile("cp.async.commit_group;");
}
__device__ __forceinline__ void cp_wait2() {
    asm volatile("cp.async.wait_group 2;");
}
__device__ __forceinline__ void ldx4(uint32_t* r, uint32_t addr) {
    asm volatile("ldmatrix.sync.aligned.m8n8.x4.shared.b16 {%0,%1,%2,%3}, [%4];"
                 : "=r"(r[0]), "=r"(r[1]), "=r"(r[2]), "=r"(r[3]) : "r"(addr));
}
__device__ __forceinline__ void mma16816(float* d, const uint32_t* a,
                                         const uint32_t* b) {
    asm volatile(
        "mma.sync.aligned.m16n8k16.row.col.f32.f16.f16.f32 "
        "{%0,%1,%2,%3}, {%4,%5,%6,%7}, {%8,%9}, {%0,%1,%2,%3};"
        : "+f"(d[0]), "+f"(d[1]), "+f"(d[2]), "+f"(d[3])
        : "r"(a[0]), "r"(a[1]), "r"(a[2]), "r"(a[3]), "r"(b[0]), "r"(b[1]));
}

// ---------------------------------------------------------------------------
// Kernel A: LN stats + fp32 -> fp16 conversion of x (one warp per row)
// ---------------------------------------------------------------------------
__global__ void ln_prep_a_kernel(const float* __restrict__ x) {
    int gw   = (blockIdx.x * blockDim.x + threadIdx.x) >> 5;
    int lane = threadIdx.x & 31;
    const float4* row = reinterpret_cast<const float4*>(x) + (size_t)gw * (DIM / 4);

    float4 v[8];
    float s = 0.f;
#pragma unroll
    for (int i = 0; i < 8; i++) {
        v[i] = row[lane + i * 32];
        s += v[i].x + v[i].y + v[i].z + v[i].w;
    }
#pragma unroll
    for (int o = 16; o > 0; o >>= 1) s += __shfl_xor_sync(0xffffffffu, s, o);
    float mu = s * (1.f / DIM);

    float q = 0.f;
#pragma unroll
    for (int i = 0; i < 8; i++) {
        float a = v[i].x - mu, b = v[i].y - mu, c = v[i].z - mu, d = v[i].w - mu;
        q += a * a + b * b + c * c + d * d;
    }
#pragma unroll
    for (int o = 16; o > 0; o >>= 1) q += __shfl_xor_sync(0xffffffffu, q, o);

    if (lane == 0) {
        float rstd = rsqrtf(q * (1.f / DIM) + 1e-5f);
        g_scale[gw] = rstd;
        g_shift[gw] = rstd * mu;
    }

    uint2* hdst = reinterpret_cast<uint2*>(g_Ah + (size_t)gw * DIM);
#pragma unroll
    for (int i = 0; i < 8; i++) {
        int idx = lane + i * 32;
        __half2 h01 = __float22half2_rn(make_float2(v[i].x, v[i].y));
        __half2 h23 = __float22half2_rn(make_float2(v[i].z, v[i].w));
        hdst[idx] = make_uint2(*reinterpret_cast<uint32_t*>(&h01),
                               *reinterpret_cast<uint32_t*>(&h23));
    }
}

// ---------------------------------------------------------------------------
// Kernel B: W' = gamma*W as fp16; s1 = sum W', s2 = beta.W + bias
// ---------------------------------------------------------------------------
__global__ void prep_w_kernel(const float* __restrict__ Wm,
                              const float* __restrict__ gamma,
                              const float* __restrict__ beta,
                              const float* __restrict__ bias) {
    int o    = (blockIdx.x * blockDim.x + threadIdx.x) >> 5;
    int lane = threadIdx.x & 31;
    if (o >= NOUT) return;

    const float4* wr = reinterpret_cast<const float4*>(Wm) + (size_t)o * (DIM / 4);
    const float4* g4 = reinterpret_cast<const float4*>(gamma);
    const float4* b4 = reinterpret_cast<const float4*>(beta);
    uint2* hdst = reinterpret_cast<uint2*>(g_Bh + (size_t)o * DIM);

    float s1 = 0.f, s2 = 0.f;
#pragma unroll
    for (int i = 0; i < 8; i++) {
        int c = lane + i * 32;
        float4 wv = wr[c], gv = g4[c], bv = b4[c];
        float v0 = wv.x * gv.x, v1 = wv.y * gv.y, v2 = wv.z * gv.z, v3 = wv.w * gv.w;
        s1 += v0 + v1 + v2 + v3;
        s2 += wv.x * bv.x + wv.y * bv.y + wv.z * bv.z + wv.w * bv.w;

        __half2 h01 = __float22half2_rn(make_float2(v0, v1));
        __half2 h23 = __float22half2_rn(make_float2(v2, v3));
        hdst[c] = make_uint2(*reinterpret_cast<uint32_t*>(&h01),
                             *reinterpret_cast<uint32_t*>(&h23));
    }
#pragma unroll
    for (int d = 16; d > 0; d >>= 1) {
        s1 += __shfl_xor_sync(0xffffffffu, s1, d);
        s2 += __shfl_xor_sync(0xffffffffu, s2, d);
    }
    if (lane == 0) {
        g_s1[o] = s1;
        g_s2[o] = s2 + bias[o];
    }
}

// ---------------------------------------------------------------------------
// Stage loader: cp.async one K-chunk (A 128x32 + B 256x32) into a SMEM stage
// ---------------------------------------------------------------------------
__device__ __forceinline__ void stage_loads(uint32_t stg, int kbase,
                                            int R0, int C0, int tid) {
#pragma unroll
    for (int p = 0; p < 2; p++) {        // A: 512 x 16B
        int u = tid + p * 256;
        int row = u >> 2, ch = u & 3;
        cpasync16(stg + OFF_A + row * ROWB + ch * 16,
                  g_Ah + (size_t)(R0 + row) * DIM + kbase + ch * 8);
    }
#pragma unroll
    for (int p = 0; p < 4; p++) {        // B: 1024 x 16B
        int u = tid + p * 256;
        int row = u >> 2, ch = u & 3;
        cpasync16(stg + OFF_B + row * ROWB + ch * 16,
                  g_Bh + (size_t)(C0 + row) * DIM + kbase + ch * 8);
    }
}

// ---------------------------------------------------------------------------
// Kernel C: fp16 HMMA GEMM, 128x256 CTA tile, 8 warps of 64x64,
// 4-stage cp.async pipeline with ONE __syncthreads per chunk
// ---------------------------------------------------------------------------
__global__ void __launch_bounds__(256, 1)
gemm_hmma_kernel(float* __restrict__ out) {
    extern __shared__ char smem[];
    const uint32_t sb = smem_u32(smem);
    const int tid = threadIdx.x;
    const int wid = tid >> 5;
    const int lid = tid & 31;
    const int R0 = blockIdx.y * TM;
    const int C0 = blockIdx.x * TN;
    const int Mb = (wid & 1) * 64;   // warp M offset (2 warps in M)
    const int Nb = (wid >> 1) * 64;  // warp N offset (4 warps in N)

    float acc[4][8][4];
#pragma unroll
    for (int mt = 0; mt < 4; mt++)
#pragma unroll
        for (int nt = 0; nt < 8; nt++)
#pragma unroll
            for (int k = 0; k < 4; k++) acc[mt][nt][k] = 0.f;

    // prologue: stages 0..2 hold chunks 0..2
#pragma unroll
    for (int s = 0; s < STAGES - 1; s++) {
        stage_loads(sb + s * STAGE_BYTES, s * BK, R0, C0, tid);
        cp_commit();
    }

    const int r16 = lid & 15;
    const int kh  = lid >> 4;

    for (int c = 0; c < NCHUNK; c++) {
        // chunk c landed when <=2 groups pending
        cp_wait2();
        __syncthreads();   // also: all warps finished reading stage (c-1)&3

        // prefetch chunk c+3 into stage (c+3)&3 == (c-1)&3 (safe after sync)
        int pre = c + STAGES - 1;
        if (pre < NCHUNK)
            stage_loads(sb + (pre & (STAGES - 1)) * STAGE_BYTES, pre * BK,
                        R0, C0, tid);
        cp_commit();

        const uint32_t stg = sb + (c & (STAGES - 1)) * STAGE_BYTES;
#pragma unroll
        for (int ks = 0; ks < 2; ks++) {
            const uint32_t koff = ks * 32 + kh * 16;

            uint32_t ah[4][4];
#pragma unroll
            for (int mt = 0; mt < 4; mt++)
                ldx4(ah[mt], stg + OFF_A + (Mb + mt * 16 + r16) * ROWB + koff);

#pragma unroll
            for (int g = 0; g < 4; g++) {   // 16 B-rows per ldx4 -> 2 n-tiles
                uint32_t qb[4];
                ldx4(qb, stg + OFF_B + (Nb + g * 16 + r16) * ROWB + koff);
                uint32_t b0[2] = {qb[0], qb[2]};
                uint32_t b1[2] = {qb[1], qb[3]};
#pragma unroll
                for (int mt = 0; mt < 4; mt++) {
                    mma16816(acc[mt][2 * g],     ah[mt], b0);
                    mma16816(acc[mt][2 * g + 1], ah[mt], b1);
                }
            }
        }
    }

    // ---- Epilogue: y = sc*acc - sh*s1[o] + s2[o], patch-split store ----
    const int q  = C0 >> 9;          // quadrant constant across this 256-col tile
    const int e1 = q >> 1, e2 = q & 1;
    const int fbase = C0 & (FPN - 1);
    const int colb  = Nb + (lid & 3) * 2;

    float2 s1v[8], s2v[8];
#pragma unroll
    for (int nt = 0; nt < 8; nt++) {
        s1v[nt] = *reinterpret_cast<const float2*>(&g_s1[C0 + colb + nt * 8]);
        s2v[nt] = *reinterpret_cast<const float2*>(&g_s2[C0 + colb + nt * 8]);
    }

#pragma unroll
    for (int mt = 0; mt < 4; mt++) {
#pragma unroll
        for (int rh = 0; rh < 2; rh++) {
            int gr = R0 + Mb + mt * 16 + rh * 8 + (lid >> 2);
            float sc = g_scale[gr];
            float sh = g_shift[gr];
            int bn = gr >> 10;
            int h  = (gr >> 5) & 31;
            int w  = gr & 31;
            float* op = out +
                (((size_t)(bn * 64 + 2 * h + e1) * 64) + (2 * w + e2)) * FPN +
                fbase + colb;
#pragma unroll
            for (int nt = 0; nt < 8; nt++) {
                float2 v;
                v.x = sc * acc[mt][nt][rh * 2]     - sh * s1v[nt].x + s2v[nt].x;
                v.y = sc * acc[mt][nt][rh * 2 + 1] - sh * s1v[nt].y + s2v[nt].y;
                *reinterpret_cast<float2*>(op + nt * 8) = v;
            }
        }
    }
}

// ---------------------------------------------------------------------------
// Launch contract
// ---------------------------------------------------------------------------
extern "C" void kernel_launch(void* const* d_in, const int* in_sizes, int n_in,
                              void* d_out, int out_size) {
    const float* x     = (const float*)d_in[0];
    const float* gamma = (const float*)d_in[1];
    const float* beta  = (const float*)d_in[2];
    const float* Wm    = (const float*)d_in[3];
    const float* bias  = (const float*)d_in[4];
    float* out = (float*)d_out;

    cudaFuncSetAttribute(gemm_hmma_kernel,
                         cudaFuncAttributeMaxDynamicSharedMemorySize, SMEM_TOTAL);

    ln_prep_a_kernel<<<MROWS / 8, 256>>>(x);
    prep_w_kernel<<<NOUT / 8, 256>>>(Wm, gamma, beta, bias);

    dim3 grid(NOUT / TN, MROWS / TM);  // (8, 512)
    gemm_hmma_kernel<<<grid, 256, SMEM_TOTAL>>>(out);
}

// round 10
// speedup vs baseline: 1.1177x; 1.1177x over previous
#include <cuda_runtime.h>
#include <cuda_fp16.h>
#include <cstdint>

// ---------------------------------------------------------------------------
// Problem constants
// ---------------------------------------------------------------------------
#define DIM    1024
#define FPN    512
#define NOUT   2048
#define MROWS  65536            // 16*4*32*32

// GEMM tiling (R8 config: best measured)
#define TM 128
#define TN 128
#define BK 32
#define NCHUNK (DIM / BK)       // 32
#define STAGES 4                // power of two -> & (STAGES-1) indexing

// SMEM: padded rows of 80B (32 fp16 = 64B data + 16B pad) -> conflict-free ldmatrix
#define ROWB 80
#define ARRB (128 * ROWB)       // 10240 bytes per array per stage
#define OFF_AH 0
#define OFF_BH (1 * ARRB)
#define STAGE_BYTES (2 * ARRB)  // 20480
#define SMEM_TOTAL (STAGES * STAGE_BYTES)  // 81920 -> 2 CTAs/SM

// ---------------------------------------------------------------------------
// Device scratch (device globals; no dynamic allocation allowed)
// ---------------------------------------------------------------------------
__device__ float g_scale[MROWS];                 // rstd
__device__ float g_shift[MROWS];                 // rstd * mu
__device__ __half g_Ah[(size_t)MROWS * DIM];     // 128 MB
__device__ __half g_Bh[(size_t)NOUT * DIM];      // 4 MB
__device__ float g_s1[NOUT];
__device__ float g_s2[NOUT];

// ---------------------------------------------------------------------------
// PTX helpers (base PTX, family-generic sm_103 safe)
// ---------------------------------------------------------------------------
__device__ __forceinline__ uint32_t smem_u32(const void* p) {
    uint32_t a;
    asm("{ .reg .u64 t; cvta.to.shared.u64 t, %1; cvt.u32.u64 %0, t; }"
        : "=r"(a) : "l"(p));
    return a;
}
__device__ __forceinline__ void cpasync16(uint32_t dst, const void* src) {
    asm volatile("cp.async.cg.shared.global [%0], [%1], 16;"
                 :: "r"(dst), "l"(src));
}
__device__ __forceinline__ void cp_commit() {
    asm volatile("cp.async.commit_group;");
}
__device__ __forceinline__ void cp_wait2() {
    asm volatile("cp.async.wait_group 2;");
}
__device__ __forceinline__ void ldx4(uint32_t* r, uint32_t addr) {
    asm volatile("ldmatrix.sync.aligned.m8n8.x4.shared.b16 {%0,%1,%2,%3}, [%4];"
                 : "=r"(r[0]), "=r"(r[1]), "=r"(r[2]), "=r"(r[3]) : "r"(addr));
}
__device__ __forceinline__ void mma16816(float* d, const uint32_t* a,
                                         const uint32_t* b) {
    asm volatile(
        "mma.sync.aligned.m16n8k16.row.col.f32.f16.f16.f32 "
        "{%0,%1,%2,%3}, {%4,%5,%6,%7}, {%8,%9}, {%0,%1,%2,%3};"
        : "+f"(d[0]), "+f"(d[1]), "+f"(d[2]), "+f"(d[3])
        : "r"(a[0]), "r"(a[1]), "r"(a[2]), "r"(a[3]), "r"(b[0]), "r"(b[1]));
}

// ---------------------------------------------------------------------------
// Merged prep kernel:
//   blocks [0, MROWS/8)          : LN stats + fp32 -> fp16 conversion of x
//   blocks [MROWS/8, +NOUT/8)    : W' = gamma*W fp16; s1, s2
// ---------------------------------------------------------------------------
#define LN_BLOCKS (MROWS / 8)
#define W_BLOCKS  (NOUT / 8)

__global__ void prep_kernel(const float* __restrict__ x,
                            const float* __restrict__ Wm,
                            const float* __restrict__ gamma,
                            const float* __restrict__ beta,
                            const float* __restrict__ bias) {
    int lane = threadIdx.x & 31;

    if (blockIdx.x < LN_BLOCKS) {
        int gw = (blockIdx.x * blockDim.x + threadIdx.x) >> 5;
        const float4* row =
            reinterpret_cast<const float4*>(x) + (size_t)gw * (DIM / 4);

        float4 v[8];
        float s = 0.f;
#pragma unroll
        for (int i = 0; i < 8; i++) {
            v[i] = row[lane + i * 32];
            s += v[i].x + v[i].y + v[i].z + v[i].w;
        }
#pragma unroll
        for (int o = 16; o > 0; o >>= 1) s += __shfl_xor_sync(0xffffffffu, s, o);
        float mu = s * (1.f / DIM);

        float q = 0.f;
#pragma unroll
        for (int i = 0; i < 8; i++) {
            float a = v[i].x - mu, b = v[i].y - mu;
            float c = v[i].z - mu, d = v[i].w - mu;
            q += a * a + b * b + c * c + d * d;
        }
#pragma unroll
        for (int o = 16; o > 0; o >>= 1) q += __shfl_xor_sync(0xffffffffu, q, o);

        if (lane == 0) {
            float rstd = rsqrtf(q * (1.f / DIM) + 1e-5f);
            g_scale[gw] = rstd;
            g_shift[gw] = rstd * mu;
        }

        uint2* hdst = reinterpret_cast<uint2*>(g_Ah + (size_t)gw * DIM);
#pragma unroll
        for (int i = 0; i < 8; i++) {
            int idx = lane + i * 32;
            __half2 h01 = __float22half2_rn(make_float2(v[i].x, v[i].y));
            __half2 h23 = __float22half2_rn(make_float2(v[i].z, v[i].w));
            hdst[idx] = make_uint2(*reinterpret_cast<uint32_t*>(&h01),
                                   *reinterpret_cast<uint32_t*>(&h23));
        }
    } else {
        int o = ((blockIdx.x - LN_BLOCKS) * blockDim.x + threadIdx.x) >> 5;
        if (o >= NOUT) return;

        const float4* wr =
            reinterpret_cast<const float4*>(Wm) + (size_t)o * (DIM / 4);
        const float4* g4 = reinterpret_cast<const float4*>(gamma);
        const float4* b4 = reinterpret_cast<const float4*>(beta);
        uint2* hdst = reinterpret_cast<uint2*>(g_Bh + (size_t)o * DIM);

        float s1 = 0.f, s2 = 0.f;
#pragma unroll
        for (int i = 0; i < 8; i++) {
            int c = lane + i * 32;
            float4 wv = wr[c], gv = g4[c], bv = b4[c];
            float v0 = wv.x * gv.x, v1 = wv.y * gv.y;
            float v2 = wv.z * gv.z, v3 = wv.w * gv.w;
            s1 += v0 + v1 + v2 + v3;
            s2 += wv.x * bv.x + wv.y * bv.y + wv.z * bv.z + wv.w * bv.w;

            __half2 h01 = __float22half2_rn(make_float2(v0, v1));
            __half2 h23 = __float22half2_rn(make_float2(v2, v3));
            hdst[c] = make_uint2(*reinterpret_cast<uint32_t*>(&h01),
                                 *reinterpret_cast<uint32_t*>(&h23));
        }
#pragma unroll
        for (int d = 16; d > 0; d >>= 1) {
            s1 += __shfl_xor_sync(0xffffffffu, s1, d);
            s2 += __shfl_xor_sync(0xffffffffu, s2, d);
        }
        if (lane == 0) {
            g_s1[o] = s1;
            g_s2[o] = s2 + bias[o];
        }
    }
}

// ---------------------------------------------------------------------------
// Stage loader: cp.async one K-chunk (A 128x32 + B 128x32) into a SMEM stage
// ---------------------------------------------------------------------------
__device__ __forceinline__ void stage_loads(uint32_t stg, int kbase,
                                            int R0, int C0, int tid) {
#pragma unroll
    for (int p = 0; p < 2; p++) {
        int u   = tid + p * 256;    // 512 units: 128 rows x 4 x 16B
        int row = u >> 2;
        int ch  = u & 3;
        uint32_t d = stg + row * ROWB + ch * 16;
        size_t ga = (size_t)(R0 + row) * DIM + kbase + ch * 8;
        size_t gb = (size_t)(C0 + row) * DIM + kbase + ch * 8;
        cpasync16(d + OFF_AH, g_Ah + ga);
        cpasync16(d + OFF_BH, g_Bh + gb);
    }
}

// ---------------------------------------------------------------------------
// Kernel C: fp16 HMMA GEMM (single product) + LN affine + patch-split
// 128x128 tile, 8 warps (32x64), BK=32, 4 stages, 2 CTAs/SM,
// ONE __syncthreads per chunk (wait -> sync -> prefetch -> compute)
// ---------------------------------------------------------------------------
__global__ void __launch_bounds__(256, 2)
gemm_hmma_kernel(float* __restrict__ out) {
    extern __shared__ char smem[];
    const uint32_t sb = smem_u32(smem);
    const int tid = threadIdx.x;
    const int wid = tid >> 5;
    const int lid = tid & 31;
    const int R0 = blockIdx.y * TM;
    const int C0 = blockIdx.x * TN;
    const int Mb = (wid & 3) * 32;   // warp M offset
    const int Nb = (wid >> 2) * 64;  // warp N offset

    float acc[2][8][4];
#pragma unroll
    for (int mt = 0; mt < 2; mt++)
#pragma unroll
        for (int nt = 0; nt < 8; nt++)
#pragma unroll
            for (int k = 0; k < 4; k++) acc[mt][nt][k] = 0.f;

    // prologue: stages 0..2 hold chunks 0..2
#pragma unroll
    for (int s = 0; s < STAGES - 1; s++) {
        stage_loads(sb + s * STAGE_BYTES, s * BK, R0, C0, tid);
        cp_commit();
    }

    const int r16 = lid & 15;
    const int kh  = lid >> 4;

    for (int c = 0; c < NCHUNK; c++) {
        // groups c, c+1, c+2 pending -> wait until <=2 pending: chunk c landed
        cp_wait2();
        __syncthreads();   // all warps also done reading stage (c-1)&3

        // prefetch chunk c+3 into stage (c+3)&3 == (c-1)&3 (safe after sync)
        int pre = c + STAGES - 1;
        if (pre < NCHUNK)
            stage_loads(sb + (pre & (STAGES - 1)) * STAGE_BYTES, pre * BK,
                        R0, C0, tid);
        cp_commit();

        const uint32_t stg = sb + (c & (STAGES - 1)) * STAGE_BYTES;
#pragma unroll
        for (int ks = 0; ks < 2; ks++) {
            const uint32_t koff = ks * 32 + kh * 16;

            uint32_t ah[2][4];
            uint32_t abase = stg + (Mb + r16) * ROWB + koff;
            ldx4(ah[0], abase + OFF_AH);
            ldx4(ah[1], abase + OFF_AH + 16 * ROWB);

            // B in two groups of 4 n-tiles (lower register pressure)
#pragma unroll
            for (int g = 0; g < 2; g++) {
                uint32_t bbase = stg + (Nb + g * 32 + r16) * ROWB + koff + OFF_BH;
                uint32_t q0[4], q1[4];
                ldx4(q0, bbase);
                ldx4(q1, bbase + 16 * ROWB);
                uint32_t bh[4][2];
                bh[0][0] = q0[0]; bh[0][1] = q0[2];
                bh[1][0] = q0[1]; bh[1][1] = q0[3];
                bh[2][0] = q1[0]; bh[2][1] = q1[2];
                bh[3][0] = q1[1]; bh[3][1] = q1[3];
#pragma unroll
                for (int mt = 0; mt < 2; mt++)
#pragma unroll
                    for (int j = 0; j < 4; j++)
                        mma16816(acc[mt][g * 4 + j], ah[mt], bh[j]);
            }
        }
    }

    // ---- Epilogue: y = sc*acc - sh*s1[o] + s2[o], patch-split store ----
    const int q  = C0 >> 9;
    const int e1 = q >> 1, e2 = q & 1;
    const int fbase = C0 & (FPN - 1);
    const int colb  = Nb + (lid & 3) * 2;

    float2 s1v[8], s2v[8];
#pragma unroll
    for (int nt = 0; nt < 8; nt++) {
        s1v[nt] = *reinterpret_cast<const float2*>(&g_s1[C0 + colb + nt * 8]);
        s2v[nt] = *reinterpret_cast<const float2*>(&g_s2[C0 + colb + nt * 8]);
    }

#pragma unroll
    for (int mt = 0; mt < 2; mt++) {
#pragma unroll
        for (int rh = 0; rh < 2; rh++) {
            int gr = R0 + Mb + mt * 16 + rh * 8 + (lid >> 2);
            float sc = g_scale[gr];
            float sh = g_shift[gr];
            int bn = gr >> 10;
            int h  = (gr >> 5) & 31;
            int w  = gr & 31;
            float* op = out +
                (((size_t)(bn * 64 + 2 * h + e1) * 64) + (2 * w + e2)) * FPN +
                fbase + colb;
#pragma unroll
            for (int nt = 0; nt < 8; nt++) {
                float2 v;
                v.x = sc * acc[mt][nt][rh * 2]     - sh * s1v[nt].x + s2v[nt].x;
                v.y = sc * acc[mt][nt][rh * 2 + 1] - sh * s1v[nt].y + s2v[nt].y;
                *reinterpret_cast<float2*>(op + nt * 8) = v;
            }
        }
    }
}

// ---------------------------------------------------------------------------
// Launch contract
// ---------------------------------------------------------------------------
extern "C" void kernel_launch(void* const* d_in, const int* in_sizes, int n_in,
                              void* d_out, int out_size) {
    const float* x     = (const float*)d_in[0];
    const float* gamma = (const float*)d_in[1];
    const float* beta  = (const float*)d_in[2];
    const float* Wm    = (const float*)d_in[3];
    const float* bias  = (const float*)d_in[4];
    float* out = (float*)d_out;

    cudaFuncSetAttribute(gemm_hmma_kernel,
                         cudaFuncAttributeMaxDynamicSharedMemorySize, SMEM_TOTAL);

    prep_kernel<<<LN_BLOCKS + W_BLOCKS, 256>>>(x, Wm, gamma, beta, bias);

    dim3 grid(NOUT / TN, MROWS / TM);  // (16, 512)
    gemm_hmma_kernel<<<grid, 256, SMEM_TOTAL>>>(out);
}

// round 11
// speedup vs baseline: 1.2254x; 1.0964x over previous
#include <cuda_runtime.h>
#include <cuda_fp16.h>
#include <cstdint>

// ---------------------------------------------------------------------------
// Problem constants
// ---------------------------------------------------------------------------
#define DIM    1024
#define FPN    512
#define NOUT   2048
#define MROWS  65536            // 16*4*32*32

// GEMM tiling: 128x128 CTA, 8 warps of 32x64, BK=64, 2 stages
#define TM 128
#define TN 128
#define BK 64
#define NCHUNK (DIM / BK)       // 16
#define STAGES 2

// SMEM: rows of 144B (64 fp16 = 128B data + 16B pad) -> conflict-free ldmatrix
// (bank phase r*36 mod 32 = {0,4,8,...,28} distinct for r=0..7)
#define ROWB 144
#define ARRB (128 * ROWB)       // 18432 bytes per array per stage
#define OFF_AH 0
#define OFF_BH (1 * ARRB)
#define STAGE_BYTES (2 * ARRB)  // 36864
#define SMEM_TOTAL (STAGES * STAGE_BYTES)  // 73728 -> 2 CTAs/SM

// ---------------------------------------------------------------------------
// Device scratch (device globals; no dynamic allocation allowed)
// ---------------------------------------------------------------------------
__device__ float g_scale[MROWS];                 // rstd
__device__ float g_shift[MROWS];                 // rstd * mu
__device__ __half g_Ah[(size_t)MROWS * DIM];     // 128 MB
__device__ __half g_Bh[(size_t)NOUT * DIM];      // 4 MB
__device__ float g_s1[NOUT];
__device__ float g_s2[NOUT];

// ---------------------------------------------------------------------------
// PTX helpers (base PTX, family-generic sm_103 safe)
// ---------------------------------------------------------------------------
__device__ __forceinline__ uint32_t smem_u32(const void* p) {
    uint32_t a;
    asm("{ .reg .u64 t; cvta.to.shared.u64 t, %1; cvt.u32.u64 %0, t; }"
        : "=r"(a) : "l"(p));
    return a;
}
__device__ __forceinline__ void cpasync16(uint32_t dst, const void* src) {
    asm volatile("cp.async.cg.shared.global [%0], [%1], 16;"
                 :: "r"(dst), "l"(src));
}
__device__ __forceinline__ void cp_commit() {
    asm volatile("cp.async.commit_group;");
}
__device__ __forceinline__ void cp_wait0() {
    asm volatile("cp.async.wait_group 0;");
}
__device__ __forceinline__ void ldx4(uint32_t* r, uint32_t addr) {
    asm volatile("ldmatrix.sync.aligned.m8n8.x4.shared.b16 {%0,%1,%2,%3}, [%4];"
                 : "=r"(r[0]), "=r"(r[1]), "=r"(r[2]), "=r"(r[3]) : "r"(addr));
}
__device__ __forceinline__ void mma16816(float* d, const uint32_t* a,
                                         const uint32_t* b) {
    asm volatile(
        "mma.sync.aligned.m16n8k16.row.col.f32.f16.f16.f32 "
        "{%0,%1,%2,%3}, {%4,%5,%6,%7}, {%8,%9}, {%0,%1,%2,%3};"
        : "+f"(d[0]), "+f"(d[1]), "+f"(d[2]), "+f"(d[3])
        : "r"(a[0]), "r"(a[1]), "r"(a[2]), "r"(a[3]), "r"(b[0]), "r"(b[1]));
}

// ---------------------------------------------------------------------------
// Merged prep kernel:
//   blocks [0, MROWS/8)          : LN stats + fp32 -> fp16 conversion of x
//   blocks [MROWS/8, +NOUT/8)    : W' = gamma*W fp16; s1, s2
// ---------------------------------------------------------------------------
#define LN_BLOCKS (MROWS / 8)
#define W_BLOCKS  (NOUT / 8)

__global__ void prep_kernel(const float* __restrict__ x,
                            const float* __restrict__ Wm,
                            const float* __restrict__ gamma,
                            const float* __restrict__ beta,
                            const float* __restrict__ bias) {
    int lane = threadIdx.x & 31;

    if (blockIdx.x < LN_BLOCKS) {
        int gw = (blockIdx.x * blockDim.x + threadIdx.x) >> 5;
        const float4* row =
            reinterpret_cast<const float4*>(x) + (size_t)gw * (DIM / 4);

        float4 v[8];
        float s = 0.f;
#pragma unroll
        for (int i = 0; i < 8; i++) {
            v[i] = row[lane + i * 32];
            s += v[i].x + v[i].y + v[i].z + v[i].w;
        }
#pragma unroll
        for (int o = 16; o > 0; o >>= 1) s += __shfl_xor_sync(0xffffffffu, s, o);
        float mu = s * (1.f / DIM);

        float q = 0.f;
#pragma unroll
        for (int i = 0; i < 8; i++) {
            float a = v[i].x - mu, b = v[i].y - mu;
            float c = v[i].z - mu, d = v[i].w - mu;
            q += a * a + b * b + c * c + d * d;
        }
#pragma unroll
        for (int o = 16; o > 0; o >>= 1) q += __shfl_xor_sync(0xffffffffu, q, o);

        if (lane == 0) {
            float rstd = rsqrtf(q * (1.f / DIM) + 1e-5f);
            g_scale[gw] = rstd;
            g_shift[gw] = rstd * mu;
        }

        uint2* hdst = reinterpret_cast<uint2*>(g_Ah + (size_t)gw * DIM);
#pragma unroll
        for (int i = 0; i < 8; i++) {
            int idx = lane + i * 32;
            __half2 h01 = __float22half2_rn(make_float2(v[i].x, v[i].y));
            __half2 h23 = __float22half2_rn(make_float2(v[i].z, v[i].w));
            hdst[idx] = make_uint2(*reinterpret_cast<uint32_t*>(&h01),
                                   *reinterpret_cast<uint32_t*>(&h23));
        }
    } else {
        int o = ((blockIdx.x - LN_BLOCKS) * blockDim.x + threadIdx.x) >> 5;
        if (o >= NOUT) return;

        const float4* wr =
            reinterpret_cast<const float4*>(Wm) + (size_t)o * (DIM / 4);
        const float4* g4 = reinterpret_cast<const float4*>(gamma);
        const float4* b4 = reinterpret_cast<const float4*>(beta);
        uint2* hdst = reinterpret_cast<uint2*>(g_Bh + (size_t)o * DIM);

        float s1 = 0.f, s2 = 0.f;
#pragma unroll
        for (int i = 0; i < 8; i++) {
            int c = lane + i * 32;
            float4 wv = wr[c], gv = g4[c], bv = b4[c];
            float v0 = wv.x * gv.x, v1 = wv.y * gv.y;
            float v2 = wv.z * gv.z, v3 = wv.w * gv.w;
            s1 += v0 + v1 + v2 + v3;
            s2 += wv.x * bv.x + wv.y * bv.y + wv.z * bv.z + wv.w * bv.w;

            __half2 h01 = __float22half2_rn(make_float2(v0, v1));
            __half2 h23 = __float22half2_rn(make_float2(v2, v3));
            hdst[c] = make_uint2(*reinterpret_cast<uint32_t*>(&h01),
                                 *reinterpret_cast<uint32_t*>(&h23));
        }
#pragma unroll
        for (int d = 16; d > 0; d >>= 1) {
            s1 += __shfl_xor_sync(0xffffffffu, s1, d);
            s2 += __shfl_xor_sync(0xffffffffu, s2, d);
        }
        if (lane == 0) {
            g_s1[o] = s1;
            g_s2[o] = s2 + bias[o];
        }
    }
}

// ---------------------------------------------------------------------------
// Stage loader: cp.async one K=64 chunk (A 128x64 + B 128x64) into a stage
// 2048 x 16B ops over 256 threads = 8 per thread
// ---------------------------------------------------------------------------
__device__ __forceinline__ void stage_loads(uint32_t stg, int kbase,
                                            int R0, int C0, int tid) {
#pragma unroll
    for (int p = 0; p < 4; p++) {
        int u   = tid + p * 256;    // 1024 units: 128 rows x 8 x 16B
        int row = u >> 3;
        int ch  = u & 7;
        uint32_t d = stg + row * ROWB + ch * 16;
        size_t ga = (size_t)(R0 + row) * DIM + kbase + ch * 8;
        size_t gb = (size_t)(C0 + row) * DIM + kbase + ch * 8;
        cpasync16(d + OFF_AH, g_Ah + ga);
        cpasync16(d + OFF_BH, g_Bh + gb);
    }
}

// ---------------------------------------------------------------------------
// Kernel C: fp16 HMMA GEMM + LN affine + patch-split
// 128x128 tile, 8 warps (32x64), BK=64, 2 stages, 2 CTAs/SM,
// ONE __syncthreads per chunk; loads of c+1 overlap compute of c
// ---------------------------------------------------------------------------
__global__ void __launch_bounds__(256, 2)
gemm_hmma_kernel(float* __restrict__ out) {
    extern __shared__ char smem[];
    const uint32_t sb = smem_u32(smem);
    const int tid = threadIdx.x;
    const int wid = tid >> 5;
    const int lid = tid & 31;
    const int R0 = blockIdx.y * TM;
    const int C0 = blockIdx.x * TN;
    const int Mb = (wid & 3) * 32;   // warp M offset
    const int Nb = (wid >> 2) * 64;  // warp N offset

    float acc[2][8][4];
#pragma unroll
    for (int mt = 0; mt < 2; mt++)
#pragma unroll
        for (int nt = 0; nt < 8; nt++)
#pragma unroll
            for (int k = 0; k < 4; k++) acc[mt][nt][k] = 0.f;

    // prologue: stage 0 holds chunk 0
    stage_loads(sb, 0, R0, C0, tid);
    cp_commit();

    const int r16 = lid & 15;
    const int kh  = lid >> 4;

    for (int c = 0; c < NCHUNK; c++) {
        // only the group for chunk c is pending here
        cp_wait0();
        __syncthreads();   // all warps done reading stage (c+1)&1 (compute c-1)

        // issue loads for chunk c+1 into the other stage; overlaps compute c
        if (c + 1 < NCHUNK) {
            stage_loads(sb + ((c + 1) & 1) * STAGE_BYTES, (c + 1) * BK,
                        R0, C0, tid);
            cp_commit();
        }

        const uint32_t stg = sb + (c & 1) * STAGE_BYTES;
#pragma unroll
        for (int ks = 0; ks < 4; ks++) {     // 4 independent k16 steps
            const uint32_t koff = ks * 32 + kh * 16;

            uint32_t ah[2][4];
            uint32_t abase = stg + (Mb + r16) * ROWB + koff;
            ldx4(ah[0], abase + OFF_AH);
            ldx4(ah[1], abase + OFF_AH + 16 * ROWB);

#pragma unroll
            for (int g = 0; g < 2; g++) {
                uint32_t bbase = stg + (Nb + g * 32 + r16) * ROWB + koff + OFF_BH;
                uint32_t q0[4], q1[4];
                ldx4(q0, bbase);
                ldx4(q1, bbase + 16 * ROWB);
                uint32_t bh[4][2];
                bh[0][0] = q0[0]; bh[0][1] = q0[2];
                bh[1][0] = q0[1]; bh[1][1] = q0[3];
                bh[2][0] = q1[0]; bh[2][1] = q1[2];
                bh[3][0] = q1[1]; bh[3][1] = q1[3];
#pragma unroll
                for (int mt = 0; mt < 2; mt++)
#pragma unroll
                    for (int j = 0; j < 4; j++)
                        mma16816(acc[mt][g * 4 + j], ah[mt], bh[j]);
            }
        }
    }

    // ---- Epilogue: y = sc*acc - sh*s1[o] + s2[o], patch-split store ----
    const int q  = C0 >> 9;
    const int e1 = q >> 1, e2 = q & 1;
    const int fbase = C0 & (FPN - 1);
    const int colb  = Nb + (lid & 3) * 2;

    float2 s1v[8], s2v[8];
#pragma unroll
    for (int nt = 0; nt < 8; nt++) {
        s1v[nt] = *reinterpret_cast<const float2*>(&g_s1[C0 + colb + nt * 8]);
        s2v[nt] = *reinterpret_cast<const float2*>(&g_s2[C0 + colb + nt * 8]);
    }

#pragma unroll
    for (int mt = 0; mt < 2; mt++) {
#pragma unroll
        for (int rh = 0; rh < 2; rh++) {
            int gr = R0 + Mb + mt * 16 + rh * 8 + (lid >> 2);
            float sc = g_scale[gr];
            float sh = g_shift[gr];
            int bn = gr >> 10;
            int h  = (gr >> 5) & 31;
            int w  = gr & 31;
            float* op = out +
                (((size_t)(bn * 64 + 2 * h + e1) * 64) + (2 * w + e2)) * FPN +
                fbase + colb;
#pragma unroll
            for (int nt = 0; nt < 8; nt++) {
                float2 v;
                v.x = sc * acc[mt][nt][rh * 2]     - sh * s1v[nt].x + s2v[nt].x;
                v.y = sc * acc[mt][nt][rh * 2 + 1] - sh * s1v[nt].y + s2v[nt].y;
                *reinterpret_cast<float2*>(op + nt * 8) = v;
            }
        }
    }
}

// ---------------------------------------------------------------------------
// Launch contract
// ---------------------------------------------------------------------------
extern "C" void kernel_launch(void* const* d_in, const int* in_sizes, int n_in,
                              void* d_out, int out_size) {
    const float* x     = (const float*)d_in[0];
    const float* gamma = (const float*)d_in[1];
    const float* beta  = (const float*)d_in[2];
    const float* Wm    = (const float*)d_in[3];
    const float* bias  = (const float*)d_in[4];
    float* out = (float*)d_out;

    cudaFuncSetAttribute(gemm_hmma_kernel,
                         cudaFuncAttributeMaxDynamicSharedMemorySize, SMEM_TOTAL);

    prep_kernel<<<LN_BLOCKS + W_BLOCKS, 256>>>(x, Wm, gamma, beta, bias);

    dim3 grid(NOUT / TN, MROWS / TM);  // (16, 512)
    gemm_hmma_kernel<<<grid, 256, SMEM_TOTAL>>>(out);
}